// round 4
// baseline (speedup 1.0000x reference)
#include <cuda_runtime.h>

#define BATCH    4096
#define IN_FEAT  4096
#define NPAIRS_TOTAL 767   // 256 + 255 + 256
#define RPT 8

typedef unsigned long long ull;

// ---------------- scratch (device globals; no allocation allowed) ----------------
__device__ float g_h[(size_t)BATCH * IN_FEAT];        // 64 MB intermediate h
__device__ float g_gred[(size_t)NPAIRS_TOTAL * 1024]; // per (layer,pair): G1[512] | G2[512]

// ---------------- packed f32x2 helpers ----------------
__device__ __forceinline__ ull pack2(float c) {
    ull r; asm("mov.b64 %0, {%1, %1};" : "=l"(r) : "f"(c)); return r;
}
__device__ __forceinline__ void fma2(ull& d, ull a, ull b) {
    asm("fma.rn.f32x2 %0, %1, %2, %3;" : "=l"(d) : "l"(a), "l"(b), "l"(d));
}
__device__ __forceinline__ float2 unpack2(ull v) {
    float2 f; asm("mov.b64 {%0, %1}, %2;" : "=f"(f.x), "=f"(f.y) : "l"(v)); return f;
}

// ---------------- gate reduction for one pair (256 threads) ----------------
__device__ __forceinline__ void reduce_one_pair(int gb, const float* __restrict__ src,
                                                float* __restrict__ sG)
{
    int tid = threadIdx.x;
    float acc[16];
#pragma unroll
    for (int t = 0; t < 16; t++) acc[t] = 0.f;
#pragma unroll
    for (int rc = 0; rc < 16; rc++) {
        const float* p = src + rc * 4096;
#pragma unroll
        for (int t = 0; t < 16; t++) acc[t] += p[t * 256 + tid];
    }
#pragma unroll
    for (int t = 0; t < 16; t++) sG[t * 256 + tid] = acc[t];
    __syncthreads();

    float* dst = g_gred + (size_t)gb * 1024;
#pragma unroll
    for (int u = 0; u < 2; u++) {
        int o = u * 256 + tid;          // 0..511
        float s1 = 0.f;
#pragma unroll
        for (int n = 0; n < 8; n++) s1 += sG[o * 8 + n];
        dst[o] = s1;                     // G1[ij][m]
        int ij = o >> 3, nn = o & 7;
        float s2 = 0.f;
#pragma unroll
        for (int m = 0; m < 8; m++) s2 += sG[ij * 64 + m * 8 + nn];
        dst[512 + o] = s2;               // G2[ij][n]
    }
}

// ---------------- Prep kernel: gates0 reduction + permuted gather ----------------
__global__ __launch_bounds__(256) void prep_kernel(
    const float* __restrict__ g0,
    const float* __restrict__ x, const int* __restrict__ perm)
{
    __shared__ float sG[4096];
    if (blockIdx.x < 256) {
        reduce_one_pair(blockIdx.x, g0 + (size_t)blockIdx.x * 65536, sG);
        return;
    }
    int b = blockIdx.x - 256;
    const float* xr = x + (size_t)b * IN_FEAT;
    float* hr = g_h + (size_t)b * IN_FEAT;
    int tid = threadIdx.x;
#pragma unroll
    for (int c = 0; c < 16; c++) {
        int q = c * 256 + tid;
        hr[q] = xr[perm[q]];
    }
}

// ---------------- Layer kernel: RPT=8, two passes over ij ----------------
// 256-thread blocks; thread handles 8 batch rows for one pair k.
// Pass 1: y1 (G1 half, 2 LDS.128/iter); Pass 2: y2 (G2 half).
// Gate crossbar bytes per fma halved vs RPT=4 single-pass.
// FUSE_REDUCE: leading 511 blocks (y==0) reduce gates for layers 1-2,
// overlapping DRAM-bound reduction with compute-bound layer-0 work.
template<int OFFSET, bool EPI, bool FUSE_REDUCE>
__global__ __launch_bounds__(256) void layer_kernel(
    int gate_base,
    const float* __restrict__ g1r, const float* __restrict__ g2r,
    const float* __restrict__ alphap,
    const float* __restrict__ scale,
    const float* __restrict__ bias,
    float* __restrict__ out)
{
    __shared__ float sG[4096];

    int kx = blockIdx.x;
    if (FUSE_REDUCE) {
        if (kx < 511) {
            if (blockIdx.y == 0) {
                int gb = 256 + kx;
                const float* src = (gb < 511) ? g1r + (size_t)(gb - 256) * 65536
                                              : g2r + (size_t)(gb - 511) * 65536;
                reduce_one_pair(gb, src, sG);
            }
            return;
        }
        kx -= 511;
    }
    const int k = kx;

    // stage this pair's 1024 gate floats into SMEM (4KB)
    ((float4*)sG)[threadIdx.x] =
        ((const float4*)(g_gred + (size_t)(gate_base + k) * 1024))[threadIdx.x];
    __syncthreads();

    const size_t col = ((size_t)(OFFSET + 2 * k)) * 8;   // 16 contiguous floats
    const int r0 = blockIdx.y * (256 * RPT) + threadIdx.x;

    float x1[RPT][8], x2[RPT][8];
#pragma unroll
    for (int rr = 0; rr < RPT; rr++) {
        const float4* hp = (const float4*)(g_h + (size_t)(r0 + rr * 256) * IN_FEAT + col);
        float4 a0 = hp[0], a1 = hp[1], b0 = hp[2], b1 = hp[3];
        x1[rr][0]=a0.x; x1[rr][1]=a0.y; x1[rr][2]=a0.z; x1[rr][3]=a0.w;
        x1[rr][4]=a1.x; x1[rr][5]=a1.y; x1[rr][6]=a1.z; x1[rr][7]=a1.w;
        x2[rr][0]=b0.x; x2[rr][1]=b0.y; x2[rr][2]=b0.z; x2[rr][3]=b0.w;
        x2[rr][4]=b1.x; x2[rr][5]=b1.y; x2[rr][6]=b1.z; x2[rr][7]=b1.w;
    }

    float al = 1.f;
    if (EPI) al = __ldg(alphap);

    const ulonglong2* sgv = (const ulonglong2*)sG;   // 16B = 2 packed f32x2

    ull acc[RPT][4];

    // ================= PASS 1: y1 (gate half G1) =================
#pragma unroll
    for (int rr = 0; rr < RPT; rr++)
#pragma unroll
        for (int t = 0; t < 4; t++) acc[rr][t] = 0ull;

#pragma unroll
    for (int i = 0; i < 8; i++) {
#pragma unroll
        for (int j = 0; j < 8; j++) {
            const int ij = i * 8 + j;
            ulonglong2 p = sgv[ij * 2];        // G1[ij][0..3]
            ulonglong2 q = sgv[ij * 2 + 1];    // G1[ij][4..7]
#pragma unroll
            for (int rr = 0; rr < RPT; rr++) {
                ull cd = pack2(x1[rr][i] * x2[rr][j]);
                fma2(acc[rr][0], cd, p.x); fma2(acc[rr][1], cd, p.y);
                fma2(acc[rr][2], cd, q.x); fma2(acc[rr][3], cd, q.y);
            }
        }
    }
    {
        float sc[8], bi[8];
        if (EPI) {
#pragma unroll
            for (int t = 0; t < 8; t++) { sc[t] = __ldg(scale + col + t); bi[t] = __ldg(bias + col + t); }
        }
#pragma unroll
        for (int rr = 0; rr < RPT; rr++) {
            float y[8];
#pragma unroll
            for (int t = 0; t < 4; t++) {
                float2 f = unpack2(acc[rr][t]); y[2 * t] = f.x; y[2 * t + 1] = f.y;
            }
            size_t base = (size_t)(r0 + rr * 256) * IN_FEAT + col;
            if (!EPI) {
                float4* hp = (float4*)(g_h + base);
                hp[0] = make_float4(y[0], y[1], y[2], y[3]);
                hp[1] = make_float4(y[4], y[5], y[6], y[7]);
            } else {
#pragma unroll
                for (int t = 0; t < 8; t++) y[t] = al * y[t] * sc[t] + bi[t];
                float4* op = (float4*)(out + base);
                op[0] = make_float4(y[0], y[1], y[2], y[3]);
                op[1] = make_float4(y[4], y[5], y[6], y[7]);
            }
        }
    }

    // ================= PASS 2: y2 (gate half G2) =================
#pragma unroll
    for (int rr = 0; rr < RPT; rr++)
#pragma unroll
        for (int t = 0; t < 4; t++) acc[rr][t] = 0ull;

#pragma unroll
    for (int i = 0; i < 8; i++) {
#pragma unroll
        for (int j = 0; j < 8; j++) {
            const int ij = i * 8 + j;
            ulonglong2 p = sgv[128 + ij * 2];      // G2[ij][0..3]
            ulonglong2 q = sgv[128 + ij * 2 + 1];  // G2[ij][4..7]
#pragma unroll
            for (int rr = 0; rr < RPT; rr++) {
                ull cd = pack2(x1[rr][i] * x2[rr][j]);
                fma2(acc[rr][0], cd, p.x); fma2(acc[rr][1], cd, p.y);
                fma2(acc[rr][2], cd, q.x); fma2(acc[rr][3], cd, q.y);
            }
        }
    }
    {
        float sc[8], bi[8];
        if (EPI) {
#pragma unroll
            for (int t = 0; t < 8; t++) { sc[t] = __ldg(scale + col + 8 + t); bi[t] = __ldg(bias + col + 8 + t); }
        }
#pragma unroll
        for (int rr = 0; rr < RPT; rr++) {
            float y[8];
#pragma unroll
            for (int t = 0; t < 4; t++) {
                float2 f = unpack2(acc[rr][t]); y[2 * t] = f.x; y[2 * t + 1] = f.y;
            }
            size_t base = (size_t)(r0 + rr * 256) * IN_FEAT + col + 8;
            if (!EPI) {
                float4* hp = (float4*)(g_h + base);
                hp[0] = make_float4(y[0], y[1], y[2], y[3]);
                hp[1] = make_float4(y[4], y[5], y[6], y[7]);
            } else {
#pragma unroll
                for (int t = 0; t < 8; t++) y[t] = al * y[t] * sc[t] + bi[t];
                float4* op = (float4*)(out + base);
                op[0] = make_float4(y[0], y[1], y[2], y[3]);
                op[1] = make_float4(y[4], y[5], y[6], y[7]);
            }
        }
    }
}

// ---------------- launch ----------------
extern "C" void kernel_launch(void* const* d_in, const int* in_sizes, int n_in,
                              void* d_out, int out_size)
{
    (void)in_sizes; (void)n_in; (void)out_size;
    const float* x     = (const float*)d_in[0];
    const float* g0    = (const float*)d_in[1];
    const float* g1    = (const float*)d_in[2];
    const float* g2    = (const float*)d_in[3];
    const float* alpha = (const float*)d_in[4];
    const float* scale = (const float*)d_in[5];
    const float* bias  = (const float*)d_in[6];
    const int*   perm  = (const int*)d_in[7];
    float* out = (float*)d_out;

    // prep: gates0 reduce (256 blocks, scheduled first) + permuted gather (4096 blocks)
    prep_kernel<<<256 + BATCH, 256>>>(g0, x, perm);
    // layer 0: 511 leading reduce blocks (gates1+gates2) + 256 pair-blocks x 2 row-groups
    layer_kernel<0, false, true ><<<dim3(511 + 256, 2), 256>>>(0,   g1, g2, nullptr, nullptr, nullptr, nullptr);
    layer_kernel<1, false, false><<<dim3(255, 2),       256>>>(256, nullptr, nullptr, nullptr, nullptr, nullptr, nullptr);
    layer_kernel<0, true,  false><<<dim3(256, 2),       256>>>(511, nullptr, nullptr, alpha, scale, bias, out);
}

// round 5
// speedup vs baseline: 1.3777x; 1.3777x over previous
#include <cuda_runtime.h>

#define BATCH    4096
#define IN_FEAT  4096
#define NPAIRS_TOTAL 767   // 256 + 255 + 256
#define RPT 8
#define LTHREADS 128

typedef unsigned long long ull;

// ---------------- scratch (device globals; no allocation allowed) ----------------
__device__ float g_h[(size_t)BATCH * IN_FEAT];        // 64 MB intermediate h
__device__ float g_gred[(size_t)NPAIRS_TOTAL * 1024]; // per (layer,pair): G1[512] | G2[512]

// ---------------- packed f32x2 helpers ----------------
__device__ __forceinline__ ull pack2(float c) {
    ull r; asm("mov.b64 %0, {%1, %1};" : "=l"(r) : "f"(c)); return r;
}
__device__ __forceinline__ void fma2(ull& d, ull a, ull b) {
    asm("fma.rn.f32x2 %0, %1, %2, %3;" : "=l"(d) : "l"(a), "l"(b), "l"(d));
}
__device__ __forceinline__ float2 unpack2(ull v) {
    float2 f; asm("mov.b64 {%0, %1}, %2;" : "=f"(f.x), "=f"(f.y) : "l"(v)); return f;
}

// ---------------- gate reduction for one pair, 256-thread version ----------------
__device__ __forceinline__ void reduce_one_pair_256(int gb, const float* __restrict__ src,
                                                    float* __restrict__ sG)
{
    int tid = threadIdx.x;
    float acc[16];
#pragma unroll
    for (int t = 0; t < 16; t++) acc[t] = 0.f;
#pragma unroll
    for (int rc = 0; rc < 16; rc++) {
        const float* p = src + rc * 4096;
#pragma unroll
        for (int t = 0; t < 16; t++) acc[t] += p[t * 256 + tid];
    }
#pragma unroll
    for (int t = 0; t < 16; t++) sG[t * 256 + tid] = acc[t];
    __syncthreads();

    float* dst = g_gred + (size_t)gb * 1024;
#pragma unroll
    for (int u = 0; u < 2; u++) {
        int o = u * 256 + tid;          // 0..511
        float s1 = 0.f;
#pragma unroll
        for (int n = 0; n < 8; n++) s1 += sG[o * 8 + n];
        dst[o] = s1;                     // G1[ij][m]
        int ij = o >> 3, nn = o & 7;
        float s2 = 0.f;
#pragma unroll
        for (int m = 0; m < 8; m++) s2 += sG[ij * 64 + m * 8 + nn];
        dst[512 + o] = s2;               // G2[ij][n]
    }
}

// ---------------- gate reduction for one pair, 128-thread version ----------------
__device__ __forceinline__ void reduce_one_pair_128(int gb, const float* __restrict__ src,
                                                    float* __restrict__ sG)
{
    int tid = threadIdx.x;
    float acc[32];
#pragma unroll
    for (int t = 0; t < 32; t++) acc[t] = 0.f;
#pragma unroll
    for (int rc = 0; rc < 16; rc++) {
        const float* p = src + rc * 4096;
#pragma unroll
        for (int t = 0; t < 32; t++) acc[t] += p[t * 128 + tid];
    }
#pragma unroll
    for (int t = 0; t < 32; t++) sG[t * 128 + tid] = acc[t];
    __syncthreads();

    float* dst = g_gred + (size_t)gb * 1024;
#pragma unroll
    for (int u = 0; u < 4; u++) {
        int o = u * 128 + tid;          // 0..511
        float s1 = 0.f;
#pragma unroll
        for (int n = 0; n < 8; n++) s1 += sG[o * 8 + n];
        dst[o] = s1;                     // G1[ij][m]
        int ij = o >> 3, nn = o & 7;
        float s2 = 0.f;
#pragma unroll
        for (int m = 0; m < 8; m++) s2 += sG[ij * 64 + m * 8 + nn];
        dst[512 + o] = s2;               // G2[ij][n]
    }
}

// ---------------- Prep kernel: gates0 reduction + permuted gather ----------------
__global__ __launch_bounds__(256) void prep_kernel(
    const float* __restrict__ g0,
    const float* __restrict__ x, const int* __restrict__ perm)
{
    __shared__ float sG[4096];
    if (blockIdx.x < 256) {
        reduce_one_pair_256(blockIdx.x, g0 + (size_t)blockIdx.x * 65536, sG);
        return;
    }
    int b = blockIdx.x - 256;
    const float* xr = x + (size_t)b * IN_FEAT;
    float* hr = g_h + (size_t)b * IN_FEAT;
    int tid = threadIdx.x;
#pragma unroll
    for (int c = 0; c < 16; c++) {
        int q = c * 256 + tid;
        hr[q] = xr[perm[q]];
    }
}

// ---------------- Layer kernel: 128 threads, RPT=8, two passes over ij ----------------
// __launch_bounds__(128,1): allow up to 255 regs (R4's 256-thread version was
// capped at 128 regs -> spills -> 3.6TB/s local traffic). Working set ~215 regs.
// Per (ij, pass): 2 LDS.128 broadcast (8 SM-crossbar-cyc) feed 8 rows x
// (FMUL + pack + 4 FFMA2) -> fma-bound at ~0.4 crossbar:fma ratio.
// FUSE_REDUCE: leading 511 blocks (y==0) reduce gates for layers 1-2,
// overlapping their DRAM time with layer-0 compute.
template<int OFFSET, bool EPI, bool FUSE_REDUCE>
__global__ __launch_bounds__(LTHREADS, 1) void layer_kernel(
    int gate_base,
    const float* __restrict__ g1r, const float* __restrict__ g2r,
    const float* __restrict__ alphap,
    const float* __restrict__ scale,
    const float* __restrict__ bias,
    float* __restrict__ out)
{
    __shared__ float sG[4096];

    int kx = blockIdx.x;
    if (FUSE_REDUCE) {
        if (kx < 511) {
            if (blockIdx.y == 0) {
                int gb = 256 + kx;
                const float* src = (gb < 511) ? g1r + (size_t)(gb - 256) * 65536
                                              : g2r + (size_t)(gb - 511) * 65536;
                reduce_one_pair_128(gb, src, sG);
            }
            return;
        }
        kx -= 511;
    }
    const int k = kx;

    // stage this pair's 1024 gate floats into SMEM (4KB)
    {
        const float4* gsrc = (const float4*)(g_gred + (size_t)(gate_base + k) * 1024);
        ((float4*)sG)[threadIdx.x]       = gsrc[threadIdx.x];
        ((float4*)sG)[threadIdx.x + 128] = gsrc[threadIdx.x + 128];
    }
    __syncthreads();

    const size_t col = ((size_t)(OFFSET + 2 * k)) * 8;   // 16 contiguous floats
    const int r0 = blockIdx.y * (LTHREADS * RPT) + threadIdx.x;

    float x1[RPT][8], x2[RPT][8];
#pragma unroll
    for (int rr = 0; rr < RPT; rr++) {
        const float4* hp = (const float4*)(g_h + (size_t)(r0 + rr * LTHREADS) * IN_FEAT + col);
        float4 a0 = hp[0], a1 = hp[1], b0 = hp[2], b1 = hp[3];
        x1[rr][0]=a0.x; x1[rr][1]=a0.y; x1[rr][2]=a0.z; x1[rr][3]=a0.w;
        x1[rr][4]=a1.x; x1[rr][5]=a1.y; x1[rr][6]=a1.z; x1[rr][7]=a1.w;
        x2[rr][0]=b0.x; x2[rr][1]=b0.y; x2[rr][2]=b0.z; x2[rr][3]=b0.w;
        x2[rr][4]=b1.x; x2[rr][5]=b1.y; x2[rr][6]=b1.z; x2[rr][7]=b1.w;
    }

    float al = 1.f;
    if (EPI) al = __ldg(alphap);

    const ulonglong2* sgv = (const ulonglong2*)sG;   // 16B = 2 packed f32x2

    ull acc[RPT][4];

    // ================= PASS 1: y1 (gate half G1) =================
#pragma unroll
    for (int rr = 0; rr < RPT; rr++)
#pragma unroll
        for (int t = 0; t < 4; t++) acc[rr][t] = 0ull;

#pragma unroll
    for (int i = 0; i < 8; i++) {
#pragma unroll
        for (int j = 0; j < 8; j++) {
            const int ij = i * 8 + j;
            ulonglong2 p = sgv[ij * 2];        // G1[ij][0..3]
            ulonglong2 q = sgv[ij * 2 + 1];    // G1[ij][4..7]
#pragma unroll
            for (int rr = 0; rr < RPT; rr++) {
                ull cd = pack2(x1[rr][i] * x2[rr][j]);
                fma2(acc[rr][0], cd, p.x); fma2(acc[rr][1], cd, p.y);
                fma2(acc[rr][2], cd, q.x); fma2(acc[rr][3], cd, q.y);
            }
        }
    }
    {
        float sc[8], bi[8];
        if (EPI) {
#pragma unroll
            for (int t = 0; t < 8; t++) { sc[t] = __ldg(scale + col + t); bi[t] = __ldg(bias + col + t); }
        }
#pragma unroll
        for (int rr = 0; rr < RPT; rr++) {
            float y[8];
#pragma unroll
            for (int t = 0; t < 4; t++) {
                float2 f = unpack2(acc[rr][t]); y[2 * t] = f.x; y[2 * t + 1] = f.y;
            }
            size_t base = (size_t)(r0 + rr * LTHREADS) * IN_FEAT + col;
            if (!EPI) {
                float4* hp = (float4*)(g_h + base);
                hp[0] = make_float4(y[0], y[1], y[2], y[3]);
                hp[1] = make_float4(y[4], y[5], y[6], y[7]);
            } else {
#pragma unroll
                for (int t = 0; t < 8; t++) y[t] = al * y[t] * sc[t] + bi[t];
                float4* op = (float4*)(out + base);
                op[0] = make_float4(y[0], y[1], y[2], y[3]);
                op[1] = make_float4(y[4], y[5], y[6], y[7]);
            }
        }
    }

    // ================= PASS 2: y2 (gate half G2) =================
#pragma unroll
    for (int rr = 0; rr < RPT; rr++)
#pragma unroll
        for (int t = 0; t < 4; t++) acc[rr][t] = 0ull;

#pragma unroll
    for (int i = 0; i < 8; i++) {
#pragma unroll
        for (int j = 0; j < 8; j++) {
            const int ij = i * 8 + j;
            ulonglong2 p = sgv[128 + ij * 2];      // G2[ij][0..3]
            ulonglong2 q = sgv[128 + ij * 2 + 1];  // G2[ij][4..7]
#pragma unroll
            for (int rr = 0; rr < RPT; rr++) {
                ull cd = pack2(x1[rr][i] * x2[rr][j]);
                fma2(acc[rr][0], cd, p.x); fma2(acc[rr][1], cd, p.y);
                fma2(acc[rr][2], cd, q.x); fma2(acc[rr][3], cd, q.y);
            }
        }
    }
    {
        float sc[8], bi[8];
        if (EPI) {
#pragma unroll
            for (int t = 0; t < 8; t++) { sc[t] = __ldg(scale + col + 8 + t); bi[t] = __ldg(bias + col + 8 + t); }
        }
#pragma unroll
        for (int rr = 0; rr < RPT; rr++) {
            float y[8];
#pragma unroll
            for (int t = 0; t < 4; t++) {
                float2 f = unpack2(acc[rr][t]); y[2 * t] = f.x; y[2 * t + 1] = f.y;
            }
            size_t base = (size_t)(r0 + rr * LTHREADS) * IN_FEAT + col + 8;
            if (!EPI) {
                float4* hp = (float4*)(g_h + base);
                hp[0] = make_float4(y[0], y[1], y[2], y[3]);
                hp[1] = make_float4(y[4], y[5], y[6], y[7]);
            } else {
#pragma unroll
                for (int t = 0; t < 8; t++) y[t] = al * y[t] * sc[t] + bi[t];
                float4* op = (float4*)(out + base);
                op[0] = make_float4(y[0], y[1], y[2], y[3]);
                op[1] = make_float4(y[4], y[5], y[6], y[7]);
            }
        }
    }
}

// ---------------- launch ----------------
extern "C" void kernel_launch(void* const* d_in, const int* in_sizes, int n_in,
                              void* d_out, int out_size)
{
    (void)in_sizes; (void)n_in; (void)out_size;
    const float* x     = (const float*)d_in[0];
    const float* g0    = (const float*)d_in[1];
    const float* g1    = (const float*)d_in[2];
    const float* g2    = (const float*)d_in[3];
    const float* alpha = (const float*)d_in[4];
    const float* scale = (const float*)d_in[5];
    const float* bias  = (const float*)d_in[6];
    const int*   perm  = (const int*)d_in[7];
    float* out = (float*)d_out;

    // prep: gates0 reduce (256 blocks, scheduled first) + permuted gather (4096 blocks)
    prep_kernel<<<256 + BATCH, 256>>>(g0, x, perm);
    // layer 0: 511 leading reduce blocks (gates1+gates2) + 256 pair-blocks x 4 row-groups
    layer_kernel<0, false, true ><<<dim3(511 + 256, 4), LTHREADS>>>(0,   g1, g2, nullptr, nullptr, nullptr, nullptr);
    layer_kernel<1, false, false><<<dim3(255, 4),       LTHREADS>>>(256, nullptr, nullptr, nullptr, nullptr, nullptr, nullptr);
    layer_kernel<0, true,  false><<<dim3(256, 4),       LTHREADS>>>(511, nullptr, nullptr, alpha, scale, bias, out);
}

// round 6
// speedup vs baseline: 2.5731x; 1.8676x over previous
#include <cuda_runtime.h>

#define BATCH    4096
#define IN_FEAT  4096
#define NPAIRS_TOTAL 767   // 256 + 255 + 256
#define RPT 4
#define LTHREADS 128

typedef unsigned long long ull;

// ---------------- scratch (device globals; no allocation allowed) ----------------
__device__ float g_h[(size_t)BATCH * IN_FEAT];        // 64 MB intermediate h
__device__ float g_gred[(size_t)NPAIRS_TOTAL * 1024]; // per (layer,pair): G1[512] | G2[512]

// ---------------- packed f32x2 helpers ----------------
__device__ __forceinline__ ull pack2(float c) {
    ull r; asm("mov.b64 %0, {%1, %1};" : "=l"(r) : "f"(c)); return r;
}
__device__ __forceinline__ void fma2(ull& d, ull a, ull b) {
    asm("fma.rn.f32x2 %0, %1, %2, %3;" : "=l"(d) : "l"(a), "l"(b), "l"(d));
}
__device__ __forceinline__ float2 unpack2(ull v) {
    float2 f; asm("mov.b64 {%0, %1}, %2;" : "=f"(f.x), "=f"(f.y) : "l"(v)); return f;
}

// ---------------- gate reduction for one pair, 256-thread version ----------------
__device__ __forceinline__ void reduce_one_pair_256(int gb, const float* __restrict__ src,
                                                    float* __restrict__ sG)
{
    int tid = threadIdx.x;
    float acc[16];
#pragma unroll
    for (int t = 0; t < 16; t++) acc[t] = 0.f;
#pragma unroll
    for (int rc = 0; rc < 16; rc++) {
        const float* p = src + rc * 4096;
#pragma unroll
        for (int t = 0; t < 16; t++) acc[t] += p[t * 256 + tid];
    }
#pragma unroll
    for (int t = 0; t < 16; t++) sG[t * 256 + tid] = acc[t];
    __syncthreads();

    float* dst = g_gred + (size_t)gb * 1024;
#pragma unroll
    for (int u = 0; u < 2; u++) {
        int o = u * 256 + tid;          // 0..511
        float s1 = 0.f;
#pragma unroll
        for (int n = 0; n < 8; n++) s1 += sG[o * 8 + n];
        dst[o] = s1;                     // G1[ij][m]
        int ij = o >> 3, nn = o & 7;
        float s2 = 0.f;
#pragma unroll
        for (int m = 0; m < 8; m++) s2 += sG[ij * 64 + m * 8 + nn];
        dst[512 + o] = s2;               // G2[ij][n]
    }
}

// ---------------- gate reduction for one pair, 128-thread version ----------------
__device__ __forceinline__ void reduce_one_pair_128(int gb, const float* __restrict__ src,
                                                    float* __restrict__ sG)
{
    int tid = threadIdx.x;
#pragma unroll 1
    for (int half = 0; half < 2; half++) {           // keep body small
        float acc[16];
#pragma unroll
        for (int t = 0; t < 16; t++) acc[t] = 0.f;
#pragma unroll 4
        for (int rc = 0; rc < 16; rc++) {
            const float* p = src + rc * 4096 + half * 2048;
#pragma unroll
            for (int t = 0; t < 16; t++) acc[t] += p[t * 128 + tid];
        }
#pragma unroll
        for (int t = 0; t < 16; t++) sG[half * 2048 + t * 128 + tid] = acc[t];
    }
    __syncthreads();

    float* dst = g_gred + (size_t)gb * 1024;
#pragma unroll
    for (int u = 0; u < 4; u++) {
        int o = u * 128 + tid;          // 0..511
        float s1 = 0.f;
#pragma unroll
        for (int n = 0; n < 8; n++) s1 += sG[o * 8 + n];
        dst[o] = s1;                     // G1[ij][m]
        int ij = o >> 3, nn = o & 7;
        float s2 = 0.f;
#pragma unroll
        for (int m = 0; m < 8; m++) s2 += sG[ij * 64 + m * 8 + nn];
        dst[512 + o] = s2;               // G2[ij][n]
    }
}

// ---------------- Prep kernel: gates0 reduction + permuted gather ----------------
__global__ __launch_bounds__(256) void prep_kernel(
    const float* __restrict__ g0,
    const float* __restrict__ x, const int* __restrict__ perm)
{
    __shared__ float sG[4096];
    if (blockIdx.x < 256) {
        reduce_one_pair_256(blockIdx.x, g0 + (size_t)blockIdx.x * 65536, sG);
        return;
    }
    int b = blockIdx.x - 256;
    const float* xr = x + (size_t)b * IN_FEAT;
    float* hr = g_h + (size_t)b * IN_FEAT;
    int tid = threadIdx.x;
#pragma unroll
    for (int c = 0; c < 16; c++) {
        int q = c * 256 + tid;
        hr[q] = xr[perm[q]];
    }
}

// ---------------- Layer kernel ----------------
// R2 math shape (RPT=4, 16 outputs/thread) but with a SMALL hot body:
// only the j-loop is unrolled; the i-loop is a real loop (body ~6KB, fits L0 I$
// -- the R1/R2/R5 fully-unrolled bodies were 40-90KB, blowing out the I-cache
// and capping issue at ~30%). Runtime-i x1 access goes through SMEM
// (512 rows x 9-float pad -> conflict-free LDS.32); x2 + accs stay in regs.
// FUSE_REDUCE: leading 511 blocks (y==0) reduce gates for layers 1-2.
template<int OFFSET, bool EPI, bool FUSE_REDUCE>
__global__ __launch_bounds__(LTHREADS, 3) void layer_kernel(
    int gate_base,
    const float* __restrict__ g1r, const float* __restrict__ g2r,
    const float* __restrict__ alphap,
    const float* __restrict__ scale,
    const float* __restrict__ bias,
    float* __restrict__ out)
{
    __shared__ float sS[1024 + 512 * 9];   // 4KB gates | 18KB x1 staging (>=16KB for reduce)

    int kx = blockIdx.x;
    if (FUSE_REDUCE) {
        if (kx < 511) {
            if (blockIdx.y == 0) {
                int gb = 256 + kx;
                const float* src = (gb < 511) ? g1r + (size_t)(gb - 256) * 65536
                                              : g2r + (size_t)(gb - 511) * 65536;
                reduce_one_pair_128(gb, src, sS);
            }
            return;
        }
        kx -= 511;
    }
    const int k = kx;
    const int tid = threadIdx.x;

    // stage this pair's 1024 gate floats into SMEM (4KB)
    {
        const float4* gsrc = (const float4*)(g_gred + (size_t)(gate_base + k) * 1024);
        ((float4*)sS)[tid]       = gsrc[tid];
        ((float4*)sS)[tid + 128] = gsrc[tid + 128];
    }
    float* sX = sS + 1024;

    const size_t col = ((size_t)(OFFSET + 2 * k)) * 8;   // 16 contiguous floats
    const int r0 = blockIdx.y * (LTHREADS * RPT) + tid;

    float x2r[RPT][8];
#pragma unroll
    for (int rr = 0; rr < RPT; rr++) {
        const float4* hp = (const float4*)(g_h + (size_t)(r0 + rr * LTHREADS) * IN_FEAT + col);
        float4 a0 = hp[0], a1 = hp[1], b0 = hp[2], b1 = hp[3];
        int rl = tid + rr * LTHREADS;          // local row 0..511
        float* xw = sX + rl * 9;
        xw[0]=a0.x; xw[1]=a0.y; xw[2]=a0.z; xw[3]=a0.w;
        xw[4]=a1.x; xw[5]=a1.y; xw[6]=a1.z; xw[7]=a1.w;
        x2r[rr][0]=b0.x; x2r[rr][1]=b0.y; x2r[rr][2]=b0.z; x2r[rr][3]=b0.w;
        x2r[rr][4]=b1.x; x2r[rr][5]=b1.y; x2r[rr][6]=b1.z; x2r[rr][7]=b1.w;
    }
    __syncthreads();

    ull acc1[RPT][4], acc2[RPT][4];
#pragma unroll
    for (int rr = 0; rr < RPT; rr++)
#pragma unroll
        for (int t = 0; t < 4; t++) { acc1[rr][t] = 0ull; acc2[rr][t] = 0ull; }

    const ulonglong2* sgv = (const ulonglong2*)sS;   // 16B = 2 packed f32x2

#pragma unroll 1
    for (int i = 0; i < 8; i++) {
        float x1v[RPT];
#pragma unroll
        for (int rr = 0; rr < RPT; rr++) x1v[rr] = sX[(tid + rr * LTHREADS) * 9 + i];
#pragma unroll
        for (int j = 0; j < 8; j++) {
            const int ij = i * 8 + j;
            ulonglong2 p = sgv[ij * 2];            // G1[ij][0..3]
            ulonglong2 q = sgv[ij * 2 + 1];        // G1[ij][4..7]
            ulonglong2 r = sgv[128 + ij * 2];      // G2[ij][0..3]
            ulonglong2 s = sgv[128 + ij * 2 + 1];  // G2[ij][4..7]
#pragma unroll
            for (int rr = 0; rr < RPT; rr++) {
                ull cd = pack2(x1v[rr] * x2r[rr][j]);
                fma2(acc1[rr][0], cd, p.x); fma2(acc1[rr][1], cd, p.y);
                fma2(acc1[rr][2], cd, q.x); fma2(acc1[rr][3], cd, q.y);
                fma2(acc2[rr][0], cd, r.x); fma2(acc2[rr][1], cd, r.y);
                fma2(acc2[rr][2], cd, s.x); fma2(acc2[rr][3], cd, s.y);
            }
        }
    }

    float al = 1.f;
    float sc[16], bi[16];
    if (EPI) {
        al = __ldg(alphap);
#pragma unroll
        for (int t = 0; t < 16; t++) { sc[t] = __ldg(scale + col + t); bi[t] = __ldg(bias + col + t); }
    }

#pragma unroll
    for (int rr = 0; rr < RPT; rr++) {
        float y[16];
#pragma unroll
        for (int t = 0; t < 4; t++) {
            float2 f1 = unpack2(acc1[rr][t]); y[2 * t]     = f1.x; y[2 * t + 1]     = f1.y;
            float2 f2 = unpack2(acc2[rr][t]); y[8 + 2 * t] = f2.x; y[8 + 2 * t + 1] = f2.y;
        }
        size_t base = (size_t)(r0 + rr * LTHREADS) * IN_FEAT + col;
        if (!EPI) {
            float4* hp = (float4*)(g_h + base);
            hp[0] = make_float4(y[0], y[1], y[2], y[3]);
            hp[1] = make_float4(y[4], y[5], y[6], y[7]);
            hp[2] = make_float4(y[8], y[9], y[10], y[11]);
            hp[3] = make_float4(y[12], y[13], y[14], y[15]);
        } else {
#pragma unroll
            for (int t = 0; t < 16; t++) y[t] = al * y[t] * sc[t] + bi[t];
            float4* op = (float4*)(out + base);
            op[0] = make_float4(y[0], y[1], y[2], y[3]);
            op[1] = make_float4(y[4], y[5], y[6], y[7]);
            op[2] = make_float4(y[8], y[9], y[10], y[11]);
            op[3] = make_float4(y[12], y[13], y[14], y[15]);
        }
    }
}

// ---------------- launch ----------------
extern "C" void kernel_launch(void* const* d_in, const int* in_sizes, int n_in,
                              void* d_out, int out_size)
{
    (void)in_sizes; (void)n_in; (void)out_size;
    const float* x     = (const float*)d_in[0];
    const float* g0    = (const float*)d_in[1];
    const float* g1    = (const float*)d_in[2];
    const float* g2    = (const float*)d_in[3];
    const float* alpha = (const float*)d_in[4];
    const float* scale = (const float*)d_in[5];
    const float* bias  = (const float*)d_in[6];
    const int*   perm  = (const int*)d_in[7];
    float* out = (float*)d_out;

    // prep: gates0 reduce (256 blocks, scheduled first) + permuted gather (4096 blocks)
    prep_kernel<<<256 + BATCH, 256>>>(g0, x, perm);
    // layer 0: 511 leading reduce blocks (gates1+gates2) + 256 pair-blocks x 8 row-groups
    layer_kernel<0, false, true ><<<dim3(511 + 256, 8), LTHREADS>>>(0,   g1, g2, nullptr, nullptr, nullptr, nullptr);
    layer_kernel<1, false, false><<<dim3(255, 8),       LTHREADS>>>(256, nullptr, nullptr, nullptr, nullptr, nullptr, nullptr);
    layer_kernel<0, true,  false><<<dim3(256, 8),       LTHREADS>>>(511, nullptr, nullptr, alpha, scale, bias, out);
}